// round 13
// baseline (speedup 1.0000x reference)
#include <cuda_runtime.h>
#include <cuda_fp16.h>
#include <math.h>
#include <stdint.h>
#include <mma.h>

using namespace nvcuda;

// Problem constants
#define BB   2
#define SSQ  2048
#define HH   2048
#define NHH  16
#define HDD  128
#define H3   6144
#define BSR  4096
#define ALPHA 0.08838834764831845f

// Scratch (all fp16)
__device__ __half g_hh[(size_t)BSR * HH];
__device__ __half g_qkv[(size_t)BSR * H3];
__device__ __half g_ctx[(size_t)BSR * HH];
__device__ __half g_wqkvt[(size_t)H3 * HH];
__device__ __half g_wdt[(size_t)HH * HH];

// ---------------------------------------------------------------------------
// Helpers
// ---------------------------------------------------------------------------
__device__ __forceinline__ uint32_t smem_u32(const void* p) {
    uint32_t a;
    asm("{ .reg .u64 t; cvta.to.shared.u64 t, %1; cvt.u32.u64 %0, t; }" : "=r"(a) : "l"(p));
    return a;
}
__device__ __forceinline__ void cp16(uint32_t dst, const void* src) {
    asm volatile("cp.async.cg.shared.global [%0], [%1], 16;" :: "r"(dst), "l"(src));
}

// ---------------------------------------------------------------------------
// fp32 -> fp16 convert (vectorized)
// ---------------------------------------------------------------------------
__global__ __launch_bounds__(256)
void f2h(const float* __restrict__ in, __half* __restrict__ out, int n) {
    int i = (blockIdx.x * 256 + threadIdx.x) * 4;
    if (i < n) {
        float4 v = *(const float4*)(in + i);
        __half2 a = __floats2half2_rn(v.x, v.y);
        __half2 b = __floats2half2_rn(v.z, v.w);
        *(__half2*)(out + i)     = a;
        *(__half2*)(out + i + 2) = b;
    }
}

// ---------------------------------------------------------------------------
// Transpose + convert to half: Wt[n][k] = half(W[k][n]).  W is [K][N].
// ---------------------------------------------------------------------------
__global__ __launch_bounds__(256)
void transpose_h(const float* __restrict__ W, __half* __restrict__ Wt,
                 int K, int N) {
    __shared__ float t[32][33];
    const int nb = blockIdx.x * 32, kb = blockIdx.y * 32;
    const int tx = threadIdx.x & 31, ty = threadIdx.x >> 5;
    #pragma unroll
    for (int i = 0; i < 32; i += 8)
        t[ty + i][tx] = W[(size_t)(kb + ty + i) * N + nb + tx];
    __syncthreads();
    #pragma unroll
    for (int i = 0; i < 32; i += 8)
        Wt[(size_t)(nb + ty + i) * K + kb + tx] = __float2half(t[tx][ty + i]);
}

// ---------------------------------------------------------------------------
// WMMA fp16 GEMM: C = A @ Wt^T + bias (+resid). A,Wt half; accum fp32.
// CTA 128x128, 8 warps (256 thr), warp tile 32x64 (2x4 frags), BK=64,
// double-buffered cp.async, 2 CTAs/SM (16 warps).
// MODE 0: C = half, bias only.  MODE 1: C = float, bias + resid.
// ---------------------------------------------------------------------------
#define BM   128
#define BN   128
#define GBK  64
#define BKH  72                               // padded stride (halves), 144 B
#define ATB  (128 * BKH * 2)                  // 18432 B
#define STB  (2 * ATB)                        // 36864 B per stage
#define GSMEM (2 * STB)                       // 73728 B (epilogue needs 65536)

template <int MODE>
__global__ __launch_bounds__(256, 2)
void gemm_h(const __half* __restrict__ A, const __half* __restrict__ Wt,
            const float* __restrict__ bias, const float* __restrict__ resid,
            void* __restrict__ Cv, int N, int K) {
    extern __shared__ char smc[];
    const uint32_t sb = smem_u32(smc);
    const int tid = threadIdx.x;
    const int bm = blockIdx.y * BM;
    const int bn = blockIdx.x * BN;
    const int NS = K / GBK;

    // loads: 8 threads per 64-half row (8x16B chunks); 32 rows per pass
    const int lrow = tid >> 3;           // 0..31
    const int lc8  = (tid & 7) << 3;     // 0,8,...,56 (halves)

    const int warp = tid >> 5;           // 0..7
    const int wm = warp & 3;             // M group (32 rows)
    const int wn = warp >> 2;            // N group (64 cols)

    wmma::fragment<wmma::accumulator, 16, 16, 16, float> acc[2][4];
    #pragma unroll
    for (int i = 0; i < 2; i++)
        #pragma unroll
        for (int j = 0; j < 4; j++) wmma::fill_fragment(acc[i][j], 0.0f);

#define LOAD_STAGE(buf, s) do {                                               \
    const size_t koff_ = (size_t)(s) * GBK;                                   \
    _Pragma("unroll")                                                         \
    for (int j_ = 0; j_ < 4; ++j_) {                                          \
        cp16(sb + (buf) * STB + ((lrow + 32 * j_) * BKH + lc8) * 2,           \
             A + (size_t)(bm + lrow + 32 * j_) * K + koff_ + lc8);            \
    }                                                                         \
    _Pragma("unroll")                                                         \
    for (int j_ = 0; j_ < 4; ++j_) {                                          \
        cp16(sb + (buf) * STB + ATB + ((lrow + 32 * j_) * BKH + lc8) * 2,     \
             Wt + (size_t)(bn + lrow + 32 * j_) * K + koff_ + lc8);           \
    }                                                                         \
    asm volatile("cp.async.commit_group;" ::: "memory");                      \
} while (0)

    LOAD_STAGE(0, 0);

    for (int s = 0; s < NS; ++s) {
        if (s + 1 < NS) {
            LOAD_STAGE((s + 1) & 1, s + 1);
            asm volatile("cp.async.wait_group 1;" ::: "memory");
        } else {
            asm volatile("cp.async.wait_group 0;" ::: "memory");
        }
        __syncthreads();

        const __half* As = (const __half*)(smc + (s & 1) * STB);
        const __half* Bs = (const __half*)(smc + (s & 1) * STB + ATB);

        #pragma unroll
        for (int kk = 0; kk < GBK / 16; ++kk) {
            const int k0 = kk * 16;
            wmma::fragment<wmma::matrix_a, 16, 16, 16, __half,
                           wmma::row_major> af[2];
            #pragma unroll
            for (int i = 0; i < 2; i++)
                wmma::load_matrix_sync(af[i],
                    As + (wm * 32 + i * 16) * BKH + k0, BKH);
            wmma::fragment<wmma::matrix_b, 16, 16, 16, __half,
                           wmma::col_major> bf[4];
            #pragma unroll
            for (int j = 0; j < 4; j++)
                wmma::load_matrix_sync(bf[j],
                    Bs + (wn * 64 + j * 16) * BKH + k0, BKH);

            #pragma unroll
            for (int i = 0; i < 2; i++)
                #pragma unroll
                for (int j = 0; j < 4; j++)
                    wmma::mma_sync(acc[i][j], af[i], bf[j], acc[i][j]);
        }
        __syncthreads();
    }

    // epilogue: stage fp32 through smem, coalesced writes
    float* esm = (float*)smc;
    #pragma unroll
    for (int i = 0; i < 2; i++)
        #pragma unroll
        for (int j = 0; j < 4; j++)
            wmma::store_matrix_sync(
                esm + (size_t)(wm * 32 + i * 16) * 128 + wn * 64 + j * 16,
                acc[i][j], 128, wmma::mem_row_major);
    __syncthreads();

    #pragma unroll
    for (int jj = 0; jj < 16; ++jj) {
        const int idx  = tid + 256 * jj;
        const int row  = idx >> 5;
        const int col4 = (idx & 31) << 2;
        float4 v = *(const float4*)(esm + row * 128 + col4);
        const float4 b4 = *(const float4*)(bias + bn + col4);
        v.x += b4.x; v.y += b4.y; v.z += b4.z; v.w += b4.w;
        if (MODE == 1) {
            const float4 r4 = *(const float4*)(resid + (size_t)(bm + row) * N + bn + col4);
            v.x += r4.x; v.y += r4.y; v.z += r4.z; v.w += r4.w;
            *(float4*)((float*)Cv + (size_t)(bm + row) * N + bn + col4) = v;
        } else {
            __half2 h0 = __floats2half2_rn(v.x, v.y);
            __half2 h1 = __floats2half2_rn(v.z, v.w);
            __half* cp = (__half*)Cv + (size_t)(bm + row) * N + bn + col4;
            *(__half2*)(cp)     = h0;
            *(__half2*)(cp + 2) = h1;
        }
    }
#undef LOAD_STAGE
}

// ---------------------------------------------------------------------------
// WMMA fp16 flash attention (unchanged from R12).
// ---------------------------------------------------------------------------
#define AQH 136
#define APS 68
#define PPH 72
#define OFF_K   34816
#define OFF_V   52224
#define OFF_S   69632
#define OFF_P   104448
#define OFF_F   122880
#define ATTN_SMEM 123392

__global__ __launch_bounds__(256, 1)
void attn_wmma(const __half* __restrict__ qkv, const float* __restrict__ alibi,
               __half* __restrict__ ctx) {
    extern __shared__ char smc[];
    __half* Qh   = (__half*)smc;
    __half* Kh   = (__half*)(smc + OFF_K);
    __half* Vh   = (__half*)(smc + OFF_V);
    float*  Ss   = (float*)(smc + OFF_S);
    __half* Ph   = (__half*)(smc + OFF_P);
    float*  fRow = (float*)(smc + OFF_F);
    float*  Of   = (float*)smc;

    const uint32_t sb = smem_u32(smc);
    const uint32_t sbQ = sb;
    const uint32_t sbK = sb + OFF_K;
    const uint32_t sbV = sb + OFF_V;

    const int tid  = threadIdx.x;
    const int warp = tid >> 5;
    const int qt = (gridDim.x - 1) - blockIdx.x;
    const int bh = blockIdx.y;
    const int b  = bh >> 4;
    const int h  = bh & 15;
    const int q0 = qt * 128;

    const size_t base = (size_t)b * SSQ * H3 + (size_t)h * (3 * HDD);

    // discover fp32-accumulator lane->row mapping (m16n16k16)
    if (tid < 256) Ss[(tid >> 4) * APS + (tid & 15)] = (float)(tid >> 4);
    __syncthreads();
    int rid[8];
    {
        wmma::fragment<wmma::accumulator, 16, 16, 16, float> rmap;
        wmma::load_matrix_sync(rmap, Ss, APS, wmma::mem_row_major);
        #pragma unroll
        for (int e = 0; e < 8; e++) rid[e] = (int)rmap.x[e];
    }

    // issue Q loads (group)
    #pragma unroll
    for (int t = 0; t < 8; t++) {
        int idx = tid + 256 * t;
        int r2  = idx >> 4;
        int c8  = (idx & 15) << 3;
        cp16(sbQ + (r2 * AQH + c8) * 2,
             qkv + base + (size_t)(q0 + r2) * H3 + HDD + c8);
    }
    asm volatile("cp.async.commit_group;" ::: "memory");

    const int omr = warp * 16;
    wmma::fragment<wmma::accumulator, 16, 16, 16, float> oacc[8];
    #pragma unroll
    for (int j = 0; j < 8; j++) wmma::fill_fragment(oacc[j], 0.0f);

    const int r   = tid >> 1;
    const int hf  = tid & 1;
    const int c0s = hf * 32;
    float mrow = -INFINITY, lrow = 0.0f;

    const float* alib = alibi + (size_t)bh * SSQ;
    const int nkt = 2 * qt + 2;

    for (int kt = 0; kt < nkt; kt++) {
        const int k0 = kt * 64;
        __syncthreads();

        // issue K (group), then V (group)
        #pragma unroll
        for (int t = 0; t < 4; t++) {
            int idx = tid + 256 * t;
            int r2  = idx >> 4;
            int c8  = (idx & 15) << 3;
            cp16(sbK + (r2 * AQH + c8) * 2,
                 qkv + base + (size_t)(k0 + r2) * H3 + c8);
        }
        asm volatile("cp.async.commit_group;" ::: "memory");
        #pragma unroll
        for (int t = 0; t < 4; t++) {
            int idx = tid + 256 * t;
            int r2  = idx >> 4;
            int c8  = (idx & 15) << 3;
            cp16(sbV + (r2 * AQH + c8) * 2,
                 qkv + base + (size_t)(k0 + r2) * H3 + 2 * HDD + c8);
        }
        asm volatile("cp.async.commit_group;" ::: "memory");

        asm volatile("cp.async.wait_group 1;" ::: "memory");
        __syncthreads();

        // S = Q @ K^T : warp tile 16 x 64, 8 k-steps of 16
        {
            wmma::fragment<wmma::accumulator, 16, 16, 16, float> sacc[4];
            #pragma unroll
            for (int j = 0; j < 4; j++) wmma::fill_fragment(sacc[j], 0.0f);
            #pragma unroll
            for (int ks = 0; ks < 8; ks++) {
                wmma::fragment<wmma::matrix_a, 16, 16, 16, __half,
                               wmma::row_major> af;
                wmma::load_matrix_sync(af, Qh + omr * AQH + ks * 16, AQH);
                #pragma unroll
                for (int j = 0; j < 4; j++) {
                    wmma::fragment<wmma::matrix_b, 16, 16, 16, __half,
                                   wmma::col_major> bf;
                    wmma::load_matrix_sync(bf, Kh + (j * 16) * AQH + ks * 16, AQH);
                    wmma::mma_sync(sacc[j], af, bf, sacc[j]);
                }
            }
            #pragma unroll
            for (int j = 0; j < 4; j++)
                wmma::store_matrix_sync(Ss + omr * APS + j * 16, sacc[j],
                                        APS, wmma::mem_row_major);
        }
        __syncthreads();

        // online softmax
        {
            float* srow = Ss + r * APS + c0s;
            __half* prow = Ph + r * PPH + c0s;
            float mt = -INFINITY;
            #pragma unroll
            for (int c = 0; c < 32; c++) {
                float v = srow[c] * ALPHA + alib[k0 + c0s + c];
                if (k0 + c0s + c > q0 + r) v = -INFINITY;
                srow[c] = v;
                mt = fmaxf(mt, v);
            }
            mt = fmaxf(mt, __shfl_xor_sync(0xffffffffu, mt, 1, 2));
            const float mn = fmaxf(mrow, mt);
            const float f  = __expf(mrow - mn);
            float ps = 0.0f;
            #pragma unroll
            for (int c = 0; c < 32; c++) {
                float p = __expf(srow[c] - mn);
                prow[c] = __float2half(p);
                ps += p;
            }
            ps += __shfl_xor_sync(0xffffffffu, ps, 1, 2);
            lrow = lrow * f + ps;
            mrow = mn;
            if (hf == 0) fRow[r] = f;
        }
        asm volatile("cp.async.wait_group 0;" ::: "memory");
        __syncthreads();

        // rescale O, then O += P @ V
        {
            float fr[8];
            #pragma unroll
            for (int e = 0; e < 8; e++) fr[e] = fRow[omr + rid[e]];
            #pragma unroll
            for (int j = 0; j < 8; j++)
                #pragma unroll
                for (int e = 0; e < 8; e++) oacc[j].x[e] *= fr[e];

            #pragma unroll
            for (int ks = 0; ks < 4; ks++) {
                wmma::fragment<wmma::matrix_a, 16, 16, 16, __half,
                               wmma::row_major> af;
                wmma::load_matrix_sync(af, Ph + omr * PPH + ks * 16, PPH);
                #pragma unroll
                for (int j = 0; j < 8; j++) {
                    wmma::fragment<wmma::matrix_b, 16, 16, 16, __half,
                                   wmma::row_major> bf;
                    wmma::load_matrix_sync(bf, Vh + (ks * 16) * AQH + j * 16, AQH);
                    wmma::mma_sync(oacc[j], af, bf, oacc[j]);
                }
            }
        }
    }

    // spill O fp32 over dead Q/K/V region, normalize, write ctx (half)
    __syncthreads();
    #pragma unroll
    for (int j = 0; j < 8; j++)
        wmma::store_matrix_sync(Of + omr * 132 + j * 16, oacc[j],
                                132, wmma::mem_row_major);
    __syncthreads();
    {
        const float inv = 1.0f / lrow;
        const int c0o = hf * 64;
        __half* crow = ctx + ((size_t)b * SSQ + q0 + r) * HH + h * HDD + c0o;
        const float* orow = Of + r * 132 + c0o;
        #pragma unroll
        for (int j = 0; j < 64; j += 2) {
            __half2 hv = __floats2half2_rn(orow[j] * inv, orow[j + 1] * inv);
            *(__half2*)(crow + j) = hv;
        }
    }
}

// ---------------------------------------------------------------------------
// Launch
// ---------------------------------------------------------------------------
extern "C" void kernel_launch(void* const* d_in, const int* in_sizes, int n_in,
                              void* d_out, int out_size) {
    (void)in_sizes; (void)n_in; (void)out_size;
    const float* hs    = (const float*)d_in[0];
    const float* resid = (const float*)d_in[2];
    const float* alibi = (const float*)d_in[3];
    const float* Wqkv  = (const float*)d_in[4];
    const float* bqkv  = (const float*)d_in[5];
    const float* Wd    = (const float*)d_in[6];
    const float* bd    = (const float*)d_in[7];
    float* out = (float*)d_out;

    __half *hh, *qkvp, *ctxp, *wqkvt, *wdt;
    cudaGetSymbolAddress((void**)&hh,    g_hh);
    cudaGetSymbolAddress((void**)&qkvp,  g_qkv);
    cudaGetSymbolAddress((void**)&ctxp,  g_ctx);
    cudaGetSymbolAddress((void**)&wqkvt, g_wqkvt);
    cudaGetSymbolAddress((void**)&wdt,   g_wdt);

    cudaFuncSetAttribute(gemm_h<0>, cudaFuncAttributeMaxDynamicSharedMemorySize, GSMEM);
    cudaFuncSetAttribute(gemm_h<1>, cudaFuncAttributeMaxDynamicSharedMemorySize, GSMEM);
    cudaFuncSetAttribute(attn_wmma, cudaFuncAttributeMaxDynamicSharedMemorySize, ATTN_SMEM);

    // 0) convert hidden -> half; transpose+convert weights -> half
    f2h<<<(BSR * HH) / 1024, 256>>>(hs, hh, BSR * HH);
    transpose_h<<<dim3(H3 / 32, HH / 32), 256>>>(Wqkv, wqkvt, HH, H3);
    transpose_h<<<dim3(HH / 32, HH / 32), 256>>>(Wd,   wdt,   HH, HH);

    // 1) qkv = hidden @ Wqkv + bqkv  (fp16 in, half out)
    gemm_h<0><<<dim3(H3 / BN, BSR / BM), 256, GSMEM>>>(
        hh, wqkvt, bqkv, nullptr, qkvp, H3, HH);

    // 2) attention (fp16 flash)
    attn_wmma<<<dim3(SSQ / 128, BB * NHH), 256, ATTN_SMEM>>>(qkvp, alibi, ctxp);

    // 3) out = ctx @ Wd + bd + residual  (fp16 in, fp32 out)
    gemm_h<1><<<dim3(HH / BN, BSR / BM), 256, GSMEM>>>(
        ctxp, wdt, bd, resid, out, HH, HH);
}

// round 14
// speedup vs baseline: 1.0422x; 1.0422x over previous
#include <cuda_runtime.h>
#include <cuda_fp16.h>
#include <math.h>
#include <stdint.h>
#include <mma.h>

using namespace nvcuda;

// Problem constants
#define BB   2
#define SSQ  2048
#define HH   2048
#define NHH  16
#define HDD  128
#define H3   6144
#define BSR  4096
#define ALPHA 0.08838834764831845f

// Scratch (all fp16)
__device__ __half g_hh[(size_t)BSR * HH];
__device__ __half g_qkv[(size_t)BSR * H3];
__device__ __half g_ctx[(size_t)BSR * HH];
__device__ __half g_wqkvt[(size_t)H3 * HH];
__device__ __half g_wdt[(size_t)HH * HH];

// ---------------------------------------------------------------------------
// Helpers
// ---------------------------------------------------------------------------
__device__ __forceinline__ uint32_t smem_u32(const void* p) {
    uint32_t a;
    asm("{ .reg .u64 t; cvta.to.shared.u64 t, %1; cvt.u32.u64 %0, t; }" : "=r"(a) : "l"(p));
    return a;
}
__device__ __forceinline__ void cp16(uint32_t dst, const void* src) {
    asm volatile("cp.async.cg.shared.global [%0], [%1], 16;" :: "r"(dst), "l"(src));
}

// ---------------------------------------------------------------------------
// fp32 -> fp16 convert (vectorized)
// ---------------------------------------------------------------------------
__global__ __launch_bounds__(256)
void f2h(const float* __restrict__ in, __half* __restrict__ out, int n) {
    int i = (blockIdx.x * 256 + threadIdx.x) * 4;
    if (i < n) {
        float4 v = *(const float4*)(in + i);
        __half2 a = __floats2half2_rn(v.x, v.y);
        __half2 b = __floats2half2_rn(v.z, v.w);
        *(__half2*)(out + i)     = a;
        *(__half2*)(out + i + 2) = b;
    }
}

// ---------------------------------------------------------------------------
// Transpose + convert to half: Wt[n][k] = half(W[k][n]).  W is [K][N].
// ---------------------------------------------------------------------------
__global__ __launch_bounds__(256)
void transpose_h(const float* __restrict__ W, __half* __restrict__ Wt,
                 int K, int N) {
    __shared__ float t[32][33];
    const int nb = blockIdx.x * 32, kb = blockIdx.y * 32;
    const int tx = threadIdx.x & 31, ty = threadIdx.x >> 5;
    #pragma unroll
    for (int i = 0; i < 32; i += 8)
        t[ty + i][tx] = W[(size_t)(kb + ty + i) * N + nb + tx];
    __syncthreads();
    #pragma unroll
    for (int i = 0; i < 32; i += 8)
        Wt[(size_t)(nb + ty + i) * K + kb + tx] = __float2half(t[tx][ty + i]);
}

// ---------------------------------------------------------------------------
// WMMA fp16 GEMM: C = A @ Wt^T + bias (+resid). A,Wt half; accum fp32.
// CTA 128x128, 4 warps (128 thr), warp tile 64x64, BK=32, 4-stage cp.async
// pipeline (prefetch distance 3).
// MODE 0: C = half, bias only.  MODE 1: C = float, bias + resid.
// ---------------------------------------------------------------------------
#define BM   128
#define BN   128
#define GBK  32
#define BKH  40                               // padded stride (halves), 80 B
#define ATB  (128 * BKH * 2)                  // 10240 B
#define STB  (2 * ATB)                        // 20480 B per stage
#define GSMEM (4 * STB)                       // 81920 B (epilogue needs 65536)

template <int MODE>
__global__ __launch_bounds__(128, 2)
void gemm_h(const __half* __restrict__ A, const __half* __restrict__ Wt,
            const float* __restrict__ bias, const float* __restrict__ resid,
            void* __restrict__ Cv, int N, int K) {
    extern __shared__ char smc[];
    const uint32_t sb = smem_u32(smc);
    const int tid = threadIdx.x;
    const int bm = blockIdx.y * BM;
    const int bn = blockIdx.x * BN;
    const int NS = K / GBK;

    // loads: 4 threads per 32-half row (4x16B chunks); 32 rows per pass
    const int lrow = tid >> 2;           // 0..31
    const int lc8  = (tid & 3) << 3;     // 0,8,16,24 (halves)

    const int warp = tid >> 5;           // 0..3
    const int wm = warp & 1;             // M half (64 rows)
    const int wn = warp >> 1;            // N half (64 cols)

    wmma::fragment<wmma::accumulator, 16, 16, 16, float> acc[4][4];
    #pragma unroll
    for (int i = 0; i < 4; i++)
        #pragma unroll
        for (int j = 0; j < 4; j++) wmma::fill_fragment(acc[i][j], 0.0f);

#define LOAD_STAGE(buf, s) do {                                               \
    const size_t koff_ = (size_t)(s) * GBK;                                   \
    _Pragma("unroll")                                                         \
    for (int j_ = 0; j_ < 4; ++j_) {                                          \
        cp16(sb + (buf) * STB + ((lrow + 32 * j_) * BKH + lc8) * 2,           \
             A + (size_t)(bm + lrow + 32 * j_) * K + koff_ + lc8);            \
    }                                                                         \
    _Pragma("unroll")                                                         \
    for (int j_ = 0; j_ < 4; ++j_) {                                          \
        cp16(sb + (buf) * STB + ATB + ((lrow + 32 * j_) * BKH + lc8) * 2,     \
             Wt + (size_t)(bn + lrow + 32 * j_) * K + koff_ + lc8);           \
    }                                                                         \
    asm volatile("cp.async.commit_group;" ::: "memory");                      \
} while (0)

    LOAD_STAGE(0, 0);
    LOAD_STAGE(1, 1);
    LOAD_STAGE(2, 2);

    for (int s = 0; s < NS; ++s) {
        if (s + 3 < NS) {
            LOAD_STAGE((s + 3) & 3, s + 3);
            asm volatile("cp.async.wait_group 3;" ::: "memory");
        } else {
            asm volatile("cp.async.wait_group 0;" ::: "memory");
        }
        __syncthreads();

        const __half* As = (const __half*)(smc + (s & 3) * STB);
        const __half* Bs = (const __half*)(smc + (s & 3) * STB + ATB);

        #pragma unroll
        for (int kk = 0; kk < GBK / 16; ++kk) {
            const int k0 = kk * 16;
            wmma::fragment<wmma::matrix_a, 16, 16, 16, __half,
                           wmma::row_major> af[4];
            #pragma unroll
            for (int i = 0; i < 4; i++)
                wmma::load_matrix_sync(af[i],
                    As + (wm * 64 + i * 16) * BKH + k0, BKH);
            wmma::fragment<wmma::matrix_b, 16, 16, 16, __half,
                           wmma::col_major> bf[4];
            #pragma unroll
            for (int j = 0; j < 4; j++)
                wmma::load_matrix_sync(bf[j],
                    Bs + (wn * 64 + j * 16) * BKH + k0, BKH);

            #pragma unroll
            for (int i = 0; i < 4; i++)
                #pragma unroll
                for (int j = 0; j < 4; j++)
                    wmma::mma_sync(acc[i][j], af[i], bf[j], acc[i][j]);
        }
        __syncthreads();
    }

    // epilogue: stage fp32 through smem, coalesced writes
    float* esm = (float*)smc;
    #pragma unroll
    for (int i = 0; i < 4; i++)
        #pragma unroll
        for (int j = 0; j < 4; j++)
            wmma::store_matrix_sync(
                esm + (size_t)(wm * 64 + i * 16) * 128 + wn * 64 + j * 16,
                acc[i][j], 128, wmma::mem_row_major);
    __syncthreads();

    #pragma unroll
    for (int jj = 0; jj < 32; ++jj) {
        const int idx  = tid + 128 * jj;
        const int row  = idx >> 5;
        const int col4 = (idx & 31) << 2;
        float4 v = *(const float4*)(esm + row * 128 + col4);
        const float4 b4 = *(const float4*)(bias + bn + col4);
        v.x += b4.x; v.y += b4.y; v.z += b4.z; v.w += b4.w;
        if (MODE == 1) {
            const float4 r4 = *(const float4*)(resid + (size_t)(bm + row) * N + bn + col4);
            v.x += r4.x; v.y += r4.y; v.z += r4.z; v.w += r4.w;
            *(float4*)((float*)Cv + (size_t)(bm + row) * N + bn + col4) = v;
        } else {
            __half2 h0 = __floats2half2_rn(v.x, v.y);
            __half2 h1 = __floats2half2_rn(v.z, v.w);
            __half* cp = (__half*)Cv + (size_t)(bm + row) * N + bn + col4;
            *(__half2*)(cp)     = h0;
            *(__half2*)(cp + 2) = h1;
        }
    }
#undef LOAD_STAGE
}

// ---------------------------------------------------------------------------
// WMMA fp16 flash attention (unchanged from R12).
// ---------------------------------------------------------------------------
#define AQH 136
#define APS 68
#define PPH 72
#define OFF_K   34816
#define OFF_V   52224
#define OFF_S   69632
#define OFF_P   104448
#define OFF_F   122880
#define ATTN_SMEM 123392

__global__ __launch_bounds__(256, 1)
void attn_wmma(const __half* __restrict__ qkv, const float* __restrict__ alibi,
               __half* __restrict__ ctx) {
    extern __shared__ char smc[];
    __half* Qh   = (__half*)smc;
    __half* Kh   = (__half*)(smc + OFF_K);
    __half* Vh   = (__half*)(smc + OFF_V);
    float*  Ss   = (float*)(smc + OFF_S);
    __half* Ph   = (__half*)(smc + OFF_P);
    float*  fRow = (float*)(smc + OFF_F);
    float*  Of   = (float*)smc;

    const uint32_t sb = smem_u32(smc);
    const uint32_t sbQ = sb;
    const uint32_t sbK = sb + OFF_K;
    const uint32_t sbV = sb + OFF_V;

    const int tid  = threadIdx.x;
    const int warp = tid >> 5;
    const int qt = (gridDim.x - 1) - blockIdx.x;
    const int bh = blockIdx.y;
    const int b  = bh >> 4;
    const int h  = bh & 15;
    const int q0 = qt * 128;

    const size_t base = (size_t)b * SSQ * H3 + (size_t)h * (3 * HDD);

    // discover fp32-accumulator lane->row mapping (m16n16k16)
    if (tid < 256) Ss[(tid >> 4) * APS + (tid & 15)] = (float)(tid >> 4);
    __syncthreads();
    int rid[8];
    {
        wmma::fragment<wmma::accumulator, 16, 16, 16, float> rmap;
        wmma::load_matrix_sync(rmap, Ss, APS, wmma::mem_row_major);
        #pragma unroll
        for (int e = 0; e < 8; e++) rid[e] = (int)rmap.x[e];
    }

    // issue Q loads (group)
    #pragma unroll
    for (int t = 0; t < 8; t++) {
        int idx = tid + 256 * t;
        int r2  = idx >> 4;
        int c8  = (idx & 15) << 3;
        cp16(sbQ + (r2 * AQH + c8) * 2,
             qkv + base + (size_t)(q0 + r2) * H3 + HDD + c8);
    }
    asm volatile("cp.async.commit_group;" ::: "memory");

    const int omr = warp * 16;
    wmma::fragment<wmma::accumulator, 16, 16, 16, float> oacc[8];
    #pragma unroll
    for (int j = 0; j < 8; j++) wmma::fill_fragment(oacc[j], 0.0f);

    const int r   = tid >> 1;
    const int hf  = tid & 1;
    const int c0s = hf * 32;
    float mrow = -INFINITY, lrow = 0.0f;

    const float* alib = alibi + (size_t)bh * SSQ;
    const int nkt = 2 * qt + 2;

    for (int kt = 0; kt < nkt; kt++) {
        const int k0 = kt * 64;
        __syncthreads();

        // issue K (group), then V (group)
        #pragma unroll
        for (int t = 0; t < 4; t++) {
            int idx = tid + 256 * t;
            int r2  = idx >> 4;
            int c8  = (idx & 15) << 3;
            cp16(sbK + (r2 * AQH + c8) * 2,
                 qkv + base + (size_t)(k0 + r2) * H3 + c8);
        }
        asm volatile("cp.async.commit_group;" ::: "memory");
        #pragma unroll
        for (int t = 0; t < 4; t++) {
            int idx = tid + 256 * t;
            int r2  = idx >> 4;
            int c8  = (idx & 15) << 3;
            cp16(sbV + (r2 * AQH + c8) * 2,
                 qkv + base + (size_t)(k0 + r2) * H3 + 2 * HDD + c8);
        }
        asm volatile("cp.async.commit_group;" ::: "memory");

        asm volatile("cp.async.wait_group 1;" ::: "memory");
        __syncthreads();

        // S = Q @ K^T : warp tile 16 x 64, 8 k-steps of 16
        {
            wmma::fragment<wmma::accumulator, 16, 16, 16, float> sacc[4];
            #pragma unroll
            for (int j = 0; j < 4; j++) wmma::fill_fragment(sacc[j], 0.0f);
            #pragma unroll
            for (int ks = 0; ks < 8; ks++) {
                wmma::fragment<wmma::matrix_a, 16, 16, 16, __half,
                               wmma::row_major> af;
                wmma::load_matrix_sync(af, Qh + omr * AQH + ks * 16, AQH);
                #pragma unroll
                for (int j = 0; j < 4; j++) {
                    wmma::fragment<wmma::matrix_b, 16, 16, 16, __half,
                                   wmma::col_major> bf;
                    wmma::load_matrix_sync(bf, Kh + (j * 16) * AQH + ks * 16, AQH);
                    wmma::mma_sync(sacc[j], af, bf, sacc[j]);
                }
            }
            #pragma unroll
            for (int j = 0; j < 4; j++)
                wmma::store_matrix_sync(Ss + omr * APS + j * 16, sacc[j],
                                        APS, wmma::mem_row_major);
        }
        __syncthreads();

        // online softmax
        {
            float* srow = Ss + r * APS + c0s;
            __half* prow = Ph + r * PPH + c0s;
            float mt = -INFINITY;
            #pragma unroll
            for (int c = 0; c < 32; c++) {
                float v = srow[c] * ALPHA + alib[k0 + c0s + c];
                if (k0 + c0s + c > q0 + r) v = -INFINITY;
                srow[c] = v;
                mt = fmaxf(mt, v);
            }
            mt = fmaxf(mt, __shfl_xor_sync(0xffffffffu, mt, 1, 2));
            const float mn = fmaxf(mrow, mt);
            const float f  = __expf(mrow - mn);
            float ps = 0.0f;
            #pragma unroll
            for (int c = 0; c < 32; c++) {
                float p = __expf(srow[c] - mn);
                prow[c] = __float2half(p);
                ps += p;
            }
            ps += __shfl_xor_sync(0xffffffffu, ps, 1, 2);
            lrow = lrow * f + ps;
            mrow = mn;
            if (hf == 0) fRow[r] = f;
        }
        asm volatile("cp.async.wait_group 0;" ::: "memory");
        __syncthreads();

        // rescale O, then O += P @ V
        {
            float fr[8];
            #pragma unroll
            for (int e = 0; e < 8; e++) fr[e] = fRow[omr + rid[e]];
            #pragma unroll
            for (int j = 0; j < 8; j++)
                #pragma unroll
                for (int e = 0; e < 8; e++) oacc[j].x[e] *= fr[e];

            #pragma unroll
            for (int ks = 0; ks < 4; ks++) {
                wmma::fragment<wmma::matrix_a, 16, 16, 16, __half,
                               wmma::row_major> af;
                wmma::load_matrix_sync(af, Ph + omr * PPH + ks * 16, PPH);
                #pragma unroll
                for (int j = 0; j < 8; j++) {
                    wmma::fragment<wmma::matrix_b, 16, 16, 16, __half,
                                   wmma::row_major> bf;
                    wmma::load_matrix_sync(bf, Vh + (ks * 16) * AQH + j * 16, AQH);
                    wmma::mma_sync(oacc[j], af, bf, oacc[j]);
                }
            }
        }
    }

    // spill O fp32 over dead Q/K/V region, normalize, write ctx (half)
    __syncthreads();
    #pragma unroll
    for (int j = 0; j < 8; j++)
        wmma::store_matrix_sync(Of + omr * 132 + j * 16, oacc[j],
                                132, wmma::mem_row_major);
    __syncthreads();
    {
        const float inv = 1.0f / lrow;
        const int c0o = hf * 64;
        __half* crow = ctx + ((size_t)b * SSQ + q0 + r) * HH + h * HDD + c0o;
        const float* orow = Of + r * 132 + c0o;
        #pragma unroll
        for (int j = 0; j < 64; j += 2) {
            __half2 hv = __floats2half2_rn(orow[j] * inv, orow[j + 1] * inv);
            *(__half2*)(crow + j) = hv;
        }
    }
}

// ---------------------------------------------------------------------------
// Launch
// ---------------------------------------------------------------------------
extern "C" void kernel_launch(void* const* d_in, const int* in_sizes, int n_in,
                              void* d_out, int out_size) {
    (void)in_sizes; (void)n_in; (void)out_size;
    const float* hs    = (const float*)d_in[0];
    const float* resid = (const float*)d_in[2];
    const float* alibi = (const float*)d_in[3];
    const float* Wqkv  = (const float*)d_in[4];
    const float* bqkv  = (const float*)d_in[5];
    const float* Wd    = (const float*)d_in[6];
    const float* bd    = (const float*)d_in[7];
    float* out = (float*)d_out;

    __half *hh, *qkvp, *ctxp, *wqkvt, *wdt;
    cudaGetSymbolAddress((void**)&hh,    g_hh);
    cudaGetSymbolAddress((void**)&qkvp,  g_qkv);
    cudaGetSymbolAddress((void**)&ctxp,  g_ctx);
    cudaGetSymbolAddress((void**)&wqkvt, g_wqkvt);
    cudaGetSymbolAddress((void**)&wdt,   g_wdt);

    cudaFuncSetAttribute(gemm_h<0>, cudaFuncAttributeMaxDynamicSharedMemorySize, GSMEM);
    cudaFuncSetAttribute(gemm_h<1>, cudaFuncAttributeMaxDynamicSharedMemorySize, GSMEM);
    cudaFuncSetAttribute(attn_wmma, cudaFuncAttributeMaxDynamicSharedMemorySize, ATTN_SMEM);

    // 0) convert hidden -> half; transpose+convert weights -> half
    f2h<<<(BSR * HH) / 1024, 256>>>(hs, hh, BSR * HH);
    transpose_h<<<dim3(H3 / 32, HH / 32), 256>>>(Wqkv, wqkvt, HH, H3);
    transpose_h<<<dim3(HH / 32, HH / 32), 256>>>(Wd,   wdt,   HH, HH);

    // 1) qkv = hidden @ Wqkv + bqkv  (fp16 in, half out)
    gemm_h<0><<<dim3(H3 / BN, BSR / BM), 128, GSMEM>>>(
        hh, wqkvt, bqkv, nullptr, qkvp, H3, HH);

    // 2) attention (fp16 flash)
    attn_wmma<<<dim3(SSQ / 128, BB * NHH), 256, ATTN_SMEM>>>(qkvp, alibi, ctxp);

    // 3) out = ctx @ Wd + bd + residual  (fp16 in, fp32 out)
    gemm_h<1><<<dim3(HH / BN, BSR / BM), 128, GSMEM>>>(
        ctxp, wdt, bd, resid, out, HH, HH);
}

// round 15
// speedup vs baseline: 1.0680x; 1.0248x over previous
#include <cuda_runtime.h>
#include <cuda_fp16.h>
#include <math.h>
#include <stdint.h>
#include <mma.h>

using namespace nvcuda;

// Problem constants
#define BB   2
#define SSQ  2048
#define HH   2048
#define NHH  16
#define HDD  128
#define H3   6144
#define BSR  4096
#define ALPHA 0.08838834764831845f

// Scratch (all fp16)
__device__ __half g_hh[(size_t)BSR * HH];
__device__ __half g_qkv[(size_t)BSR * H3];
__device__ __half g_ctx[(size_t)BSR * HH];
__device__ __half g_wqkvt[(size_t)H3 * HH];
__device__ __half g_wdt[(size_t)HH * HH];

// ---------------------------------------------------------------------------
// Helpers
// ---------------------------------------------------------------------------
__device__ __forceinline__ uint32_t smem_u32(const void* p) {
    uint32_t a;
    asm("{ .reg .u64 t; cvta.to.shared.u64 t, %1; cvt.u32.u64 %0, t; }" : "=r"(a) : "l"(p));
    return a;
}
__device__ __forceinline__ void cp16(uint32_t dst, const void* src) {
    asm volatile("cp.async.cg.shared.global [%0], [%1], 16;" :: "r"(dst), "l"(src));
}

// ---------------------------------------------------------------------------
// fp32 -> fp16 convert (vectorized)
// ---------------------------------------------------------------------------
__global__ __launch_bounds__(256)
void f2h(const float* __restrict__ in, __half* __restrict__ out, int n) {
    int i = (blockIdx.x * 256 + threadIdx.x) * 4;
    if (i < n) {
        float4 v = *(const float4*)(in + i);
        __half2 a = __floats2half2_rn(v.x, v.y);
        __half2 b = __floats2half2_rn(v.z, v.w);
        *(__half2*)(out + i)     = a;
        *(__half2*)(out + i + 2) = b;
    }
}

// ---------------------------------------------------------------------------
// Transpose + convert to half: Wt[n][k] = half(W[k][n]).  W is [K][N].
// ---------------------------------------------------------------------------
__global__ __launch_bounds__(256)
void transpose_h(const float* __restrict__ W, __half* __restrict__ Wt,
                 int K, int N) {
    __shared__ float t[32][33];
    const int nb = blockIdx.x * 32, kb = blockIdx.y * 32;
    const int tx = threadIdx.x & 31, ty = threadIdx.x >> 5;
    #pragma unroll
    for (int i = 0; i < 32; i += 8)
        t[ty + i][tx] = W[(size_t)(kb + ty + i) * N + nb + tx];
    __syncthreads();
    #pragma unroll
    for (int i = 0; i < 32; i += 8)
        Wt[(size_t)(nb + ty + i) * K + kb + tx] = __float2half(t[tx][ty + i]);
}

// ---------------------------------------------------------------------------
// WMMA fp16 GEMM (unchanged from R14): CTA 128x128, 4 warps, 64x64 warp
// tile, BK=32, 4-stage cp.async pipeline.
// ---------------------------------------------------------------------------
#define BM   128
#define BN   128
#define GBK  32
#define BKH  40
#define ATB  (128 * BKH * 2)
#define STB  (2 * ATB)
#define GSMEM (4 * STB)

template <int MODE>
__global__ __launch_bounds__(128, 2)
void gemm_h(const __half* __restrict__ A, const __half* __restrict__ Wt,
            const float* __restrict__ bias, const float* __restrict__ resid,
            void* __restrict__ Cv, int N, int K) {
    extern __shared__ char smc[];
    const uint32_t sb = smem_u32(smc);
    const int tid = threadIdx.x;
    const int bm = blockIdx.y * BM;
    const int bn = blockIdx.x * BN;
    const int NS = K / GBK;

    const int lrow = tid >> 2;
    const int lc8  = (tid & 3) << 3;

    const int warp = tid >> 5;
    const int wm = warp & 1;
    const int wn = warp >> 1;

    wmma::fragment<wmma::accumulator, 16, 16, 16, float> acc[4][4];
    #pragma unroll
    for (int i = 0; i < 4; i++)
        #pragma unroll
        for (int j = 0; j < 4; j++) wmma::fill_fragment(acc[i][j], 0.0f);

#define LOAD_STAGE(buf, s) do {                                               \
    const size_t koff_ = (size_t)(s) * GBK;                                   \
    _Pragma("unroll")                                                         \
    for (int j_ = 0; j_ < 4; ++j_) {                                          \
        cp16(sb + (buf) * STB + ((lrow + 32 * j_) * BKH + lc8) * 2,           \
             A + (size_t)(bm + lrow + 32 * j_) * K + koff_ + lc8);            \
    }                                                                         \
    _Pragma("unroll")                                                         \
    for (int j_ = 0; j_ < 4; ++j_) {                                          \
        cp16(sb + (buf) * STB + ATB + ((lrow + 32 * j_) * BKH + lc8) * 2,     \
             Wt + (size_t)(bn + lrow + 32 * j_) * K + koff_ + lc8);           \
    }                                                                         \
    asm volatile("cp.async.commit_group;" ::: "memory");                      \
} while (0)

    LOAD_STAGE(0, 0);
    LOAD_STAGE(1, 1);
    LOAD_STAGE(2, 2);

    for (int s = 0; s < NS; ++s) {
        if (s + 3 < NS) {
            LOAD_STAGE((s + 3) & 3, s + 3);
            asm volatile("cp.async.wait_group 3;" ::: "memory");
        } else {
            asm volatile("cp.async.wait_group 0;" ::: "memory");
        }
        __syncthreads();

        const __half* As = (const __half*)(smc + (s & 3) * STB);
        const __half* Bs = (const __half*)(smc + (s & 3) * STB + ATB);

        #pragma unroll
        for (int kk = 0; kk < GBK / 16; ++kk) {
            const int k0 = kk * 16;
            wmma::fragment<wmma::matrix_a, 16, 16, 16, __half,
                           wmma::row_major> af[4];
            #pragma unroll
            for (int i = 0; i < 4; i++)
                wmma::load_matrix_sync(af[i],
                    As + (wm * 64 + i * 16) * BKH + k0, BKH);
            wmma::fragment<wmma::matrix_b, 16, 16, 16, __half,
                           wmma::col_major> bf[4];
            #pragma unroll
            for (int j = 0; j < 4; j++)
                wmma::load_matrix_sync(bf[j],
                    Bs + (wn * 64 + j * 16) * BKH + k0, BKH);

            #pragma unroll
            for (int i = 0; i < 4; i++)
                #pragma unroll
                for (int j = 0; j < 4; j++)
                    wmma::mma_sync(acc[i][j], af[i], bf[j], acc[i][j]);
        }
        __syncthreads();
    }

    float* esm = (float*)smc;
    #pragma unroll
    for (int i = 0; i < 4; i++)
        #pragma unroll
        for (int j = 0; j < 4; j++)
            wmma::store_matrix_sync(
                esm + (size_t)(wm * 64 + i * 16) * 128 + wn * 64 + j * 16,
                acc[i][j], 128, wmma::mem_row_major);
    __syncthreads();

    #pragma unroll
    for (int jj = 0; jj < 32; ++jj) {
        const int idx  = tid + 128 * jj;
        const int row  = idx >> 5;
        const int col4 = (idx & 31) << 2;
        float4 v = *(const float4*)(esm + row * 128 + col4);
        const float4 b4 = *(const float4*)(bias + bn + col4);
        v.x += b4.x; v.y += b4.y; v.z += b4.z; v.w += b4.w;
        if (MODE == 1) {
            const float4 r4 = *(const float4*)(resid + (size_t)(bm + row) * N + bn + col4);
            v.x += r4.x; v.y += r4.y; v.z += r4.z; v.w += r4.w;
            *(float4*)((float*)Cv + (size_t)(bm + row) * N + bn + col4) = v;
        } else {
            __half2 h0 = __floats2half2_rn(v.x, v.y);
            __half2 h1 = __floats2half2_rn(v.z, v.w);
            __half* cp = (__half*)Cv + (size_t)(bm + row) * N + bn + col4;
            *(__half2*)(cp)     = h0;
            *(__half2*)(cp + 2) = h1;
        }
    }
#undef LOAD_STAGE
}

// ---------------------------------------------------------------------------
// WMMA fp16 flash attention — 128-col K tiles (half the barrier/softmax
// rounds of R12). CTA = (128-row Q tile, bh). 256 threads / 8 warps.
// SMEM: Qh/Kh/Vh [128][136] half, Ss [128][132] f32, Ph [128][136] half,
// fRow [128] f32 = 207360 B. S computed in two 64-col passes (sacc[4],
// same register footprint as R12).
// ---------------------------------------------------------------------------
#define AQH 136
#define APS 132
#define PPH 136
#define OFF_K   34816
#define OFF_V   69632
#define OFF_S   104448
#define OFF_P   172032
#define OFF_F   206848
#define ATTN_SMEM 207360

__global__ __launch_bounds__(256, 1)
void attn_wmma(const __half* __restrict__ qkv, const float* __restrict__ alibi,
               __half* __restrict__ ctx) {
    extern __shared__ char smc[];
    __half* Qh   = (__half*)smc;
    __half* Kh   = (__half*)(smc + OFF_K);
    __half* Vh   = (__half*)(smc + OFF_V);
    float*  Ss   = (float*)(smc + OFF_S);
    __half* Ph   = (__half*)(smc + OFF_P);
    float*  fRow = (float*)(smc + OFF_F);
    float*  Of   = (float*)smc;               // epilogue staging, stride 132

    const uint32_t sb = smem_u32(smc);
    const uint32_t sbQ = sb;
    const uint32_t sbK = sb + OFF_K;
    const uint32_t sbV = sb + OFF_V;

    const int tid  = threadIdx.x;
    const int warp = tid >> 5;
    const int qt = (gridDim.x - 1) - blockIdx.x;   // descending work order
    const int bh = blockIdx.y;
    const int b  = bh >> 4;
    const int h  = bh & 15;
    const int q0 = qt * 128;

    const size_t base = (size_t)b * SSQ * H3 + (size_t)h * (3 * HDD);

    // discover fp32-accumulator lane->row mapping (m16n16k16)
    if (tid < 256) Ss[(tid >> 4) * APS + (tid & 15)] = (float)(tid >> 4);
    __syncthreads();
    int rid[8];
    {
        wmma::fragment<wmma::accumulator, 16, 16, 16, float> rmap;
        wmma::load_matrix_sync(rmap, Ss, APS, wmma::mem_row_major);
        #pragma unroll
        for (int e = 0; e < 8; e++) rid[e] = (int)rmap.x[e];
    }

    // issue Q loads (group): 128 rows x 16 chunks of 8 halves
    #pragma unroll
    for (int t = 0; t < 8; t++) {
        int idx = tid + 256 * t;
        int r2  = idx >> 4;
        int c8  = (idx & 15) << 3;
        cp16(sbQ + (r2 * AQH + c8) * 2,
             qkv + base + (size_t)(q0 + r2) * H3 + HDD + c8);
    }
    asm volatile("cp.async.commit_group;" ::: "memory");

    const int omr = warp * 16;
    wmma::fragment<wmma::accumulator, 16, 16, 16, float> oacc[8];
    #pragma unroll
    for (int j = 0; j < 8; j++) wmma::fill_fragment(oacc[j], 0.0f);

    const int r   = tid >> 1;
    const int hf  = tid & 1;
    const int c0s = hf * 64;
    float mrow = -INFINITY, lrow = 0.0f;

    const float* alib = alibi + (size_t)bh * SSQ;

    for (int kt = 0; kt <= qt; kt++) {
        const int k0 = kt * 128;
        __syncthreads();   // prior PV reads of Vh/Ph done; probe done (kt==0)

        // issue K (group), then V (group): 128 rows x 16 chunks each
        #pragma unroll
        for (int t = 0; t < 8; t++) {
            int idx = tid + 256 * t;
            int r2  = idx >> 4;
            int c8  = (idx & 15) << 3;
            cp16(sbK + (r2 * AQH + c8) * 2,
                 qkv + base + (size_t)(k0 + r2) * H3 + c8);
        }
        asm volatile("cp.async.commit_group;" ::: "memory");
        #pragma unroll
        for (int t = 0; t < 8; t++) {
            int idx = tid + 256 * t;
            int r2  = idx >> 4;
            int c8  = (idx & 15) << 3;
            cp16(sbV + (r2 * AQH + c8) * 2,
                 qkv + base + (size_t)(k0 + r2) * H3 + 2 * HDD + c8);
        }
        asm volatile("cp.async.commit_group;" ::: "memory");

        asm volatile("cp.async.wait_group 1;" ::: "memory");   // Q+K ready
        __syncthreads();

        // S = Q @ K^T : warp tile 16 x 128, two 64-col passes (sacc[4])
        #pragma unroll
        for (int h2 = 0; h2 < 2; h2++) {
            wmma::fragment<wmma::accumulator, 16, 16, 16, float> sacc[4];
            #pragma unroll
            for (int j = 0; j < 4; j++) wmma::fill_fragment(sacc[j], 0.0f);
            #pragma unroll
            for (int ks = 0; ks < 8; ks++) {
                wmma::fragment<wmma::matrix_a, 16, 16, 16, __half,
                               wmma::row_major> af;
                wmma::load_matrix_sync(af, Qh + omr * AQH + ks * 16, AQH);
                #pragma unroll
                for (int j = 0; j < 4; j++) {
                    wmma::fragment<wmma::matrix_b, 16, 16, 16, __half,
                                   wmma::col_major> bf;
                    wmma::load_matrix_sync(bf,
                        Kh + (h2 * 64 + j * 16) * AQH + ks * 16, AQH);
                    wmma::mma_sync(sacc[j], af, bf, sacc[j]);
                }
            }
            #pragma unroll
            for (int j = 0; j < 4; j++)
                wmma::store_matrix_sync(Ss + omr * APS + h2 * 64 + j * 16,
                                        sacc[j], APS, wmma::mem_row_major);
        }
        __syncthreads();

        // online softmax: thread (r, hf) owns cols hf*64..+63 of row r
        {
            float* srow = Ss + r * APS + c0s;
            __half* prow = Ph + r * PPH + c0s;
            float mt = -INFINITY;
            #pragma unroll
            for (int c = 0; c < 64; c++) {
                float v = srow[c] * ALPHA + alib[k0 + c0s + c];
                if (k0 + c0s + c > q0 + r) v = -INFINITY;
                srow[c] = v;
                mt = fmaxf(mt, v);
            }
            mt = fmaxf(mt, __shfl_xor_sync(0xffffffffu, mt, 1, 2));
            const float mn = fmaxf(mrow, mt);
            const float f  = __expf(mrow - mn);
            float ps = 0.0f;
            #pragma unroll
            for (int c = 0; c < 64; c++) {
                float p = __expf(srow[c] - mn);
                prow[c] = __float2half(p);
                ps += p;
            }
            ps += __shfl_xor_sync(0xffffffffu, ps, 1, 2);
            lrow = lrow * f + ps;
            mrow = mn;
            if (hf == 0) fRow[r] = f;
        }
        asm volatile("cp.async.wait_group 0;" ::: "memory");   // V ready
        __syncthreads();

        // rescale O, then O += P @ V (warp tile 16 x 128, 8 k-steps)
        {
            float fr[8];
            #pragma unroll
            for (int e = 0; e < 8; e++) fr[e] = fRow[omr + rid[e]];
            #pragma unroll
            for (int j = 0; j < 8; j++)
                #pragma unroll
                for (int e = 0; e < 8; e++) oacc[j].x[e] *= fr[e];

            #pragma unroll
            for (int ks = 0; ks < 8; ks++) {
                wmma::fragment<wmma::matrix_a, 16, 16, 16, __half,
                               wmma::row_major> af;
                wmma::load_matrix_sync(af, Ph + omr * PPH + ks * 16, PPH);
                #pragma unroll
                for (int j = 0; j < 8; j++) {
                    wmma::fragment<wmma::matrix_b, 16, 16, 16, __half,
                                   wmma::row_major> bf;
                    wmma::load_matrix_sync(bf, Vh + (ks * 16) * AQH + j * 16, AQH);
                    wmma::mma_sync(oacc[j], af, bf, oacc[j]);
                }
            }
        }
    }

    // spill O fp32 over the dead Q/K region, normalize, write ctx (half)
    __syncthreads();
    #pragma unroll
    for (int j = 0; j < 8; j++)
        wmma::store_matrix_sync(Of + omr * 132 + j * 16, oacc[j],
                                132, wmma::mem_row_major);
    __syncthreads();
    {
        const float inv = 1.0f / lrow;
        const int c0o = hf * 64;
        __half* crow = ctx + ((size_t)b * SSQ + q0 + r) * HH + h * HDD + c0o;
        const float* orow = Of + r * 132 + c0o;
        #pragma unroll
        for (int j = 0; j < 64; j += 2) {
            __half2 hv = __floats2half2_rn(orow[j] * inv, orow[j + 1] * inv);
            *(__half2*)(crow + j) = hv;
        }
    }
}

// ---------------------------------------------------------------------------
// Launch
// ---------------------------------------------------------------------------
extern "C" void kernel_launch(void* const* d_in, const int* in_sizes, int n_in,
                              void* d_out, int out_size) {
    (void)in_sizes; (void)n_in; (void)out_size;
    const float* hs    = (const float*)d_in[0];
    const float* resid = (const float*)d_in[2];
    const float* alibi = (const float*)d_in[3];
    const float* Wqkv  = (const float*)d_in[4];
    const float* bqkv  = (const float*)d_in[5];
    const float* Wd    = (const float*)d_in[6];
    const float* bd    = (const float*)d_in[7];
    float* out = (float*)d_out;

    __half *hh, *qkvp, *ctxp, *wqkvt, *wdt;
    cudaGetSymbolAddress((void**)&hh,    g_hh);
    cudaGetSymbolAddress((void**)&qkvp,  g_qkv);
    cudaGetSymbolAddress((void**)&ctxp,  g_ctx);
    cudaGetSymbolAddress((void**)&wqkvt, g_wqkvt);
    cudaGetSymbolAddress((void**)&wdt,   g_wdt);

    cudaFuncSetAttribute(gemm_h<0>, cudaFuncAttributeMaxDynamicSharedMemorySize, GSMEM);
    cudaFuncSetAttribute(gemm_h<1>, cudaFuncAttributeMaxDynamicSharedMemorySize, GSMEM);
    cudaFuncSetAttribute(attn_wmma, cudaFuncAttributeMaxDynamicSharedMemorySize, ATTN_SMEM);

    // 0) convert hidden -> half; transpose+convert weights -> half
    f2h<<<(BSR * HH) / 1024, 256>>>(hs, hh, BSR * HH);
    transpose_h<<<dim3(H3 / 32, HH / 32), 256>>>(Wqkv, wqkvt, HH, H3);
    transpose_h<<<dim3(HH / 32, HH / 32), 256>>>(Wd,   wdt,   HH, HH);

    // 1) qkv = hidden @ Wqkv + bqkv  (fp16 in, half out)
    gemm_h<0><<<dim3(H3 / BN, BSR / BM), 128, GSMEM>>>(
        hh, wqkvt, bqkv, nullptr, qkvp, H3, HH);

    // 2) attention (fp16 flash, 128-col K tiles)
    attn_wmma<<<dim3(SSQ / 128, BB * NHH), 256, ATTN_SMEM>>>(qkvp, alibi, ctxp);

    // 3) out = ctx @ Wd + bd + residual  (fp16 in, fp32 out)
    gemm_h<1><<<dim3(HH / BN, BSR / BM), 128, GSMEM>>>(
        ctxp, wdt, bd, resid, out, HH, HH);
}

// round 16
// speedup vs baseline: 1.0983x; 1.0283x over previous
#include <cuda_runtime.h>
#include <cuda_fp16.h>
#include <math.h>
#include <stdint.h>
#include <mma.h>

using namespace nvcuda;

// Problem constants
#define BB   2
#define SSQ  2048
#define HH   2048
#define NHH  16
#define HDD  128
#define H3   6144
#define BSR  4096
#define ALPHA 0.08838834764831845f

// Scratch (all fp16)
__device__ __half g_hh[(size_t)BSR * HH];
__device__ __half g_qkv[(size_t)BSR * H3];
__device__ __half g_ctx[(size_t)BSR * HH];
__device__ __half g_wqkvt[(size_t)H3 * HH];
__device__ __half g_wdt[(size_t)HH * HH];

// ---------------------------------------------------------------------------
// Helpers
// ---------------------------------------------------------------------------
__device__ __forceinline__ uint32_t smem_u32(const void* p) {
    uint32_t a;
    asm("{ .reg .u64 t; cvta.to.shared.u64 t, %1; cvt.u32.u64 %0, t; }" : "=r"(a) : "l"(p));
    return a;
}
__device__ __forceinline__ void cp16(uint32_t dst, const void* src) {
    asm volatile("cp.async.cg.shared.global [%0], [%1], 16;" :: "r"(dst), "l"(src));
}

// ---------------------------------------------------------------------------
// fp32 -> fp16 convert (vectorized)
// ---------------------------------------------------------------------------
__global__ __launch_bounds__(256)
void f2h(const float* __restrict__ in, __half* __restrict__ out, int n) {
    int i = (blockIdx.x * 256 + threadIdx.x) * 4;
    if (i < n) {
        float4 v = *(const float4*)(in + i);
        __half2 a = __floats2half2_rn(v.x, v.y);
        __half2 b = __floats2half2_rn(v.z, v.w);
        *(__half2*)(out + i)     = a;
        *(__half2*)(out + i + 2) = b;
    }
}

// ---------------------------------------------------------------------------
// Transpose + convert to half: Wt[n][k] = half(W[k][n]).  W is [K][N].
// ---------------------------------------------------------------------------
__global__ __launch_bounds__(256)
void transpose_h(const float* __restrict__ W, __half* __restrict__ Wt,
                 int K, int N) {
    __shared__ float t[32][33];
    const int nb = blockIdx.x * 32, kb = blockIdx.y * 32;
    const int tx = threadIdx.x & 31, ty = threadIdx.x >> 5;
    #pragma unroll
    for (int i = 0; i < 32; i += 8)
        t[ty + i][tx] = W[(size_t)(kb + ty + i) * N + nb + tx];
    __syncthreads();
    #pragma unroll
    for (int i = 0; i < 32; i += 8)
        Wt[(size_t)(nb + ty + i) * K + kb + tx] = __float2half(t[tx][ty + i]);
}

// ---------------------------------------------------------------------------
// WMMA fp16 GEMM (unchanged from R14): CTA 128x128, 4 warps, 64x64 warp
// tile, BK=32, 4-stage cp.async pipeline.
// ---------------------------------------------------------------------------
#define BM   128
#define BN   128
#define GBK  32
#define BKH  40
#define ATB  (128 * BKH * 2)
#define STB  (2 * ATB)
#define GSMEM (4 * STB)

template <int MODE>
__global__ __launch_bounds__(128, 2)
void gemm_h(const __half* __restrict__ A, const __half* __restrict__ Wt,
            const float* __restrict__ bias, const float* __restrict__ resid,
            void* __restrict__ Cv, int N, int K) {
    extern __shared__ char smc[];
    const uint32_t sb = smem_u32(smc);
    const int tid = threadIdx.x;
    const int bm = blockIdx.y * BM;
    const int bn = blockIdx.x * BN;
    const int NS = K / GBK;

    const int lrow = tid >> 2;
    const int lc8  = (tid & 3) << 3;

    const int warp = tid >> 5;
    const int wm = warp & 1;
    const int wn = warp >> 1;

    wmma::fragment<wmma::accumulator, 16, 16, 16, float> acc[4][4];
    #pragma unroll
    for (int i = 0; i < 4; i++)
        #pragma unroll
        for (int j = 0; j < 4; j++) wmma::fill_fragment(acc[i][j], 0.0f);

#define LOAD_STAGE(buf, s) do {                                               \
    const size_t koff_ = (size_t)(s) * GBK;                                   \
    _Pragma("unroll")                                                         \
    for (int j_ = 0; j_ < 4; ++j_) {                                          \
        cp16(sb + (buf) * STB + ((lrow + 32 * j_) * BKH + lc8) * 2,           \
             A + (size_t)(bm + lrow + 32 * j_) * K + koff_ + lc8);            \
    }                                                                         \
    _Pragma("unroll")                                                         \
    for (int j_ = 0; j_ < 4; ++j_) {                                          \
        cp16(sb + (buf) * STB + ATB + ((lrow + 32 * j_) * BKH + lc8) * 2,     \
             Wt + (size_t)(bn + lrow + 32 * j_) * K + koff_ + lc8);           \
    }                                                                         \
    asm volatile("cp.async.commit_group;" ::: "memory");                      \
} while (0)

    LOAD_STAGE(0, 0);
    LOAD_STAGE(1, 1);
    LOAD_STAGE(2, 2);

    for (int s = 0; s < NS; ++s) {
        if (s + 3 < NS) {
            LOAD_STAGE((s + 3) & 3, s + 3);
            asm volatile("cp.async.wait_group 3;" ::: "memory");
        } else {
            asm volatile("cp.async.wait_group 0;" ::: "memory");
        }
        __syncthreads();

        const __half* As = (const __half*)(smc + (s & 3) * STB);
        const __half* Bs = (const __half*)(smc + (s & 3) * STB + ATB);

        #pragma unroll
        for (int kk = 0; kk < GBK / 16; ++kk) {
            const int k0 = kk * 16;
            wmma::fragment<wmma::matrix_a, 16, 16, 16, __half,
                           wmma::row_major> af[4];
            #pragma unroll
            for (int i = 0; i < 4; i++)
                wmma::load_matrix_sync(af[i],
                    As + (wm * 64 + i * 16) * BKH + k0, BKH);
            wmma::fragment<wmma::matrix_b, 16, 16, 16, __half,
                           wmma::col_major> bf[4];
            #pragma unroll
            for (int j = 0; j < 4; j++)
                wmma::load_matrix_sync(bf[j],
                    Bs + (wn * 64 + j * 16) * BKH + k0, BKH);

            #pragma unroll
            for (int i = 0; i < 4; i++)
                #pragma unroll
                for (int j = 0; j < 4; j++)
                    wmma::mma_sync(acc[i][j], af[i], bf[j], acc[i][j]);
        }
        __syncthreads();
    }

    float* esm = (float*)smc;
    #pragma unroll
    for (int i = 0; i < 4; i++)
        #pragma unroll
        for (int j = 0; j < 4; j++)
            wmma::store_matrix_sync(
                esm + (size_t)(wm * 64 + i * 16) * 128 + wn * 64 + j * 16,
                acc[i][j], 128, wmma::mem_row_major);
    __syncthreads();

    #pragma unroll
    for (int jj = 0; jj < 32; ++jj) {
        const int idx  = tid + 128 * jj;
        const int row  = idx >> 5;
        const int col4 = (idx & 31) << 2;
        float4 v = *(const float4*)(esm + row * 128 + col4);
        const float4 b4 = *(const float4*)(bias + bn + col4);
        v.x += b4.x; v.y += b4.y; v.z += b4.z; v.w += b4.w;
        if (MODE == 1) {
            const float4 r4 = *(const float4*)(resid + (size_t)(bm + row) * N + bn + col4);
            v.x += r4.x; v.y += r4.y; v.z += r4.z; v.w += r4.w;
            *(float4*)((float*)Cv + (size_t)(bm + row) * N + bn + col4) = v;
        } else {
            __half2 h0 = __floats2half2_rn(v.x, v.y);
            __half2 h1 = __floats2half2_rn(v.z, v.w);
            __half* cp = (__half*)Cv + (size_t)(bm + row) * N + bn + col4;
            *(__half2*)(cp)     = h0;
            *(__half2*)(cp + 2) = h1;
        }
    }
#undef LOAD_STAGE
}

// ---------------------------------------------------------------------------
// WMMA fp16 flash attention — 64-row Q tile, 64-col K tile, 128 threads /
// 4 warps, 2 CTAs per SM (cross-CTA phase overlap fills softmax bubbles).
// SMEM: Qh/Kh/Vh [64][136] half, Ss [64][68] f32, Ph [64][72] half,
// fRow [64] f32 = 79104 B.
// ---------------------------------------------------------------------------
#define AQH 136
#define APS 68
#define PPH 72
#define OFF_K   17408
#define OFF_V   34816
#define OFF_S   52224
#define OFF_P   69632
#define OFF_F   78848
#define ATTN_SMEM 79104

__global__ __launch_bounds__(128, 2)
void attn_wmma(const __half* __restrict__ qkv, const float* __restrict__ alibi,
               __half* __restrict__ ctx) {
    extern __shared__ char smc[];
    __half* Qh   = (__half*)smc;
    __half* Kh   = (__half*)(smc + OFF_K);
    __half* Vh   = (__half*)(smc + OFF_V);
    float*  Ss   = (float*)(smc + OFF_S);
    __half* Ph   = (__half*)(smc + OFF_P);
    float*  fRow = (float*)(smc + OFF_F);
    float*  Of   = (float*)smc;               // epilogue staging, stride 132

    const uint32_t sb = smem_u32(smc);
    const uint32_t sbQ = sb;
    const uint32_t sbK = sb + OFF_K;
    const uint32_t sbV = sb + OFF_V;

    const int tid  = threadIdx.x;
    const int warp = tid >> 5;                 // 0..3
    const int qt = (gridDim.x - 1) - blockIdx.x;   // descending work order
    const int bh = blockIdx.y;
    const int b  = bh >> 4;
    const int h  = bh & 15;
    const int q0 = qt * 64;

    const size_t base = (size_t)b * SSQ * H3 + (size_t)h * (3 * HDD);

    // discover fp32-accumulator lane->row mapping (m16n16k16)
    #pragma unroll
    for (int t = 0; t < 2; t++) {
        int idx = tid + 128 * t;
        Ss[(idx >> 4) * APS + (idx & 15)] = (float)(idx >> 4);
    }
    __syncthreads();
    int rid[8];
    {
        wmma::fragment<wmma::accumulator, 16, 16, 16, float> rmap;
        wmma::load_matrix_sync(rmap, Ss, APS, wmma::mem_row_major);
        #pragma unroll
        for (int e = 0; e < 8; e++) rid[e] = (int)rmap.x[e];
    }

    // issue Q loads (group): 64 rows x 16 chunks of 8 halves
    #pragma unroll
    for (int t = 0; t < 8; t++) {
        int idx = tid + 128 * t;
        int r2  = idx >> 4;
        int c8  = (idx & 15) << 3;
        cp16(sbQ + (r2 * AQH + c8) * 2,
             qkv + base + (size_t)(q0 + r2) * H3 + HDD + c8);
    }
    asm volatile("cp.async.commit_group;" ::: "memory");

    const int omr = warp * 16;                 // warp's 16 rows
    wmma::fragment<wmma::accumulator, 16, 16, 16, float> oacc[8];
    #pragma unroll
    for (int j = 0; j < 8; j++) wmma::fill_fragment(oacc[j], 0.0f);

    const int r   = tid >> 1;                  // 0..63
    const int hf  = tid & 1;
    const int c0s = hf * 32;
    float mrow = -INFINITY, lrow = 0.0f;

    const float* alib = alibi + (size_t)bh * SSQ;
    const int nkt = qt + 1;

    for (int kt = 0; kt < nkt; kt++) {
        const int k0 = kt * 64;
        __syncthreads();   // prior PV reads of Vh/Ph done; probe done (kt==0)

        // issue K (group), then V (group): 64 rows x 16 chunks each
        #pragma unroll
        for (int t = 0; t < 8; t++) {
            int idx = tid + 128 * t;
            int r2  = idx >> 4;
            int c8  = (idx & 15) << 3;
            cp16(sbK + (r2 * AQH + c8) * 2,
                 qkv + base + (size_t)(k0 + r2) * H3 + c8);
        }
        asm volatile("cp.async.commit_group;" ::: "memory");
        #pragma unroll
        for (int t = 0; t < 8; t++) {
            int idx = tid + 128 * t;
            int r2  = idx >> 4;
            int c8  = (idx & 15) << 3;
            cp16(sbV + (r2 * AQH + c8) * 2,
                 qkv + base + (size_t)(k0 + r2) * H3 + 2 * HDD + c8);
        }
        asm volatile("cp.async.commit_group;" ::: "memory");

        asm volatile("cp.async.wait_group 1;" ::: "memory");   // Q+K ready
        __syncthreads();

        // S = Q @ K^T : warp tile 16 x 64, 8 k-steps of 16
        {
            wmma::fragment<wmma::accumulator, 16, 16, 16, float> sacc[4];
            #pragma unroll
            for (int j = 0; j < 4; j++) wmma::fill_fragment(sacc[j], 0.0f);
            #pragma unroll
            for (int ks = 0; ks < 8; ks++) {
                wmma::fragment<wmma::matrix_a, 16, 16, 16, __half,
                               wmma::row_major> af;
                wmma::load_matrix_sync(af, Qh + omr * AQH + ks * 16, AQH);
                #pragma unroll
                for (int j = 0; j < 4; j++) {
                    wmma::fragment<wmma::matrix_b, 16, 16, 16, __half,
                                   wmma::col_major> bf;
                    wmma::load_matrix_sync(bf, Kh + (j * 16) * AQH + ks * 16, AQH);
                    wmma::mma_sync(sacc[j], af, bf, sacc[j]);
                }
            }
            #pragma unroll
            for (int j = 0; j < 4; j++)
                wmma::store_matrix_sync(Ss + omr * APS + j * 16, sacc[j],
                                        APS, wmma::mem_row_major);
        }
        __syncthreads();

        // online softmax: thread (r, hf) owns cols hf*32..+31 of row r
        {
            float* srow = Ss + r * APS + c0s;
            __half* prow = Ph + r * PPH + c0s;
            float mt = -INFINITY;
            #pragma unroll
            for (int c = 0; c < 32; c++) {
                float v = srow[c] * ALPHA + alib[k0 + c0s + c];
                if (k0 + c0s + c > q0 + r) v = -INFINITY;
                srow[c] = v;
                mt = fmaxf(mt, v);
            }
            mt = fmaxf(mt, __shfl_xor_sync(0xffffffffu, mt, 1, 2));
            const float mn = fmaxf(mrow, mt);
            const float f  = __expf(mrow - mn);
            float ps = 0.0f;
            #pragma unroll
            for (int c = 0; c < 32; c++) {
                float p = __expf(srow[c] - mn);
                prow[c] = __float2half(p);
                ps += p;
            }
            ps += __shfl_xor_sync(0xffffffffu, ps, 1, 2);
            lrow = lrow * f + ps;
            mrow = mn;
            if (hf == 0) fRow[r] = f;
        }
        asm volatile("cp.async.wait_group 0;" ::: "memory");   // V ready
        __syncthreads();

        // rescale O, then O += P @ V (warp tile 16 x 128, 4 k-steps)
        {
            float fr[8];
            #pragma unroll
            for (int e = 0; e < 8; e++) fr[e] = fRow[omr + rid[e]];
            #pragma unroll
            for (int j = 0; j < 8; j++)
                #pragma unroll
                for (int e = 0; e < 8; e++) oacc[j].x[e] *= fr[e];

            #pragma unroll
            for (int ks = 0; ks < 4; ks++) {
                wmma::fragment<wmma::matrix_a, 16, 16, 16, __half,
                               wmma::row_major> af;
                wmma::load_matrix_sync(af, Ph + omr * PPH + ks * 16, PPH);
                #pragma unroll
                for (int j = 0; j < 8; j++) {
                    wmma::fragment<wmma::matrix_b, 16, 16, 16, __half,
                                   wmma::row_major> bf;
                    wmma::load_matrix_sync(bf, Vh + (ks * 16) * AQH + j * 16, AQH);
                    wmma::mma_sync(oacc[j], af, bf, oacc[j]);
                }
            }
        }
    }

    // spill O fp32 over dead Q/K region, normalize, write ctx (half)
    __syncthreads();
    #pragma unroll
    for (int j = 0; j < 8; j++)
        wmma::store_matrix_sync(Of + omr * 132 + j * 16, oacc[j],
                                132, wmma::mem_row_major);
    __syncthreads();
    {
        const float inv = 1.0f / lrow;
        const int c0o = hf * 64;
        __half* crow = ctx + ((size_t)b * SSQ + q0 + r) * HH + h * HDD + c0o;
        const float* orow = Of + r * 132 + c0o;
        #pragma unroll
        for (int j = 0; j < 64; j += 2) {
            __half2 hv = __floats2half2_rn(orow[j] * inv, orow[j + 1] * inv);
            *(__half2*)(crow + j) = hv;
        }
    }
}

// ---------------------------------------------------------------------------
// Launch
// ---------------------------------------------------------------------------
extern "C" void kernel_launch(void* const* d_in, const int* in_sizes, int n_in,
                              void* d_out, int out_size) {
    (void)in_sizes; (void)n_in; (void)out_size;
    const float* hs    = (const float*)d_in[0];
    const float* resid = (const float*)d_in[2];
    const float* alibi = (const float*)d_in[3];
    const float* Wqkv  = (const float*)d_in[4];
    const float* bqkv  = (const float*)d_in[5];
    const float* Wd    = (const float*)d_in[6];
    const float* bd    = (const float*)d_in[7];
    float* out = (float*)d_out;

    __half *hh, *qkvp, *ctxp, *wqkvt, *wdt;
    cudaGetSymbolAddress((void**)&hh,    g_hh);
    cudaGetSymbolAddress((void**)&qkvp,  g_qkv);
    cudaGetSymbolAddress((void**)&ctxp,  g_ctx);
    cudaGetSymbolAddress((void**)&wqkvt, g_wqkvt);
    cudaGetSymbolAddress((void**)&wdt,   g_wdt);

    cudaFuncSetAttribute(gemm_h<0>, cudaFuncAttributeMaxDynamicSharedMemorySize, GSMEM);
    cudaFuncSetAttribute(gemm_h<1>, cudaFuncAttributeMaxDynamicSharedMemorySize, GSMEM);
    cudaFuncSetAttribute(attn_wmma, cudaFuncAttributeMaxDynamicSharedMemorySize, ATTN_SMEM);

    // 0) convert hidden -> half; transpose+convert weights -> half
    f2h<<<(BSR * HH) / 1024, 256>>>(hs, hh, BSR * HH);
    transpose_h<<<dim3(H3 / 32, HH / 32), 256>>>(Wqkv, wqkvt, HH, H3);
    transpose_h<<<dim3(HH / 32, HH / 32), 256>>>(Wd,   wdt,   HH, HH);

    // 1) qkv = hidden @ Wqkv + bqkv  (fp16 in, half out)
    gemm_h<0><<<dim3(H3 / BN, BSR / BM), 128, GSMEM>>>(
        hh, wqkvt, bqkv, nullptr, qkvp, H3, HH);

    // 2) attention (fp16 flash, 64-row tiles, 2 CTAs/SM)
    attn_wmma<<<dim3(SSQ / 64, BB * NHH), 128, ATTN_SMEM>>>(qkvp, alibi, ctxp);

    // 3) out = ctx @ Wd + bd + residual  (fp16 in, fp32 out)
    gemm_h<1><<<dim3(HH / BN, BSR / BM), 128, GSMEM>>>(
        ctxp, wdt, bd, resid, out, HH, HH);
}